// round 16
// baseline (speedup 1.0000x reference)
#include <cuda_runtime.h>
#include <cuda_bf16.h>
#include <math.h>
#include <stdint.h>

// Problem constants
#define BB 2
#define SS 2048
#define DD 1024
#define HH 16
#define DKK 64
#define MM (BB * SS)          // 4096
#define SCALE 0.125f          // 1/sqrt(64)

// Scratch (allocation-free rule: __device__ globals)
__device__ __nv_bfloat16 g_Qhi[BB * HH * SS * DKK];  // post-RoPE hi/lo
__device__ __nv_bfloat16 g_Qlo[BB * HH * SS * DKK];
__device__ __nv_bfloat16 g_Khi[BB * HH * SS * DKK];
__device__ __nv_bfloat16 g_Klo[BB * HH * SS * DKK];
__device__ __nv_bfloat16 g_Vthi[BB * HH * DKK * SS]; // V transposed [b,h,dk,s]
__device__ __nv_bfloat16 g_Vtlo[BB * HH * DKK * SS];
__device__ __nv_bfloat16 g_xhi[MM * DD];
__device__ __nv_bfloat16 g_xlo[MM * DD];
__device__ __nv_bfloat16 g_ahi[MM * DD];    // attention output hi/lo (O-proj input)
__device__ __nv_bfloat16 g_alo[MM * DD];
__device__ __nv_bfloat16 g_whi[4 * DD * DD]; // W^T hi: secs 0..2 = QKV, 3 = O
__device__ __nv_bfloat16 g_wlo[4 * DD * DD];

// ---------------------------------------------------------------------------
// Helpers
// ---------------------------------------------------------------------------
__device__ __forceinline__ uint32_t s2u(const void* p) {
    uint32_t a;
    asm("{ .reg .u64 t; cvta.to.shared.u64 t, %1; cvt.u32.u64 %0, t; }"
        : "=r"(a) : "l"(p));
    return a;
}
__device__ __forceinline__ void cp16(uint32_t dst, const void* src) {
    asm volatile("cp.async.cg.shared.global [%0], [%1], 16;" :: "r"(dst), "l"(src));
}
#define CP_COMMIT() asm volatile("cp.async.commit_group;" ::: "memory")
#define CP_WAIT1()  asm volatile("cp.async.wait_group 1;" ::: "memory")

__device__ __forceinline__ void mma16816(float* c, const uint32_t* a, const uint32_t* b)
{
    asm volatile(
        "mma.sync.aligned.m16n8k16.row.col.f32.bf16.bf16.f32 "
        "{%0,%1,%2,%3}, {%4,%5,%6,%7}, {%8,%9}, {%0,%1,%2,%3};"
        : "+f"(c[0]), "+f"(c[1]), "+f"(c[2]), "+f"(c[3])
        : "r"(a[0]), "r"(a[1]), "r"(a[2]), "r"(a[3]), "r"(b[0]), "r"(b[1]));
}
__device__ __forceinline__ uint32_t pack_bf2(float a, float b) {
    __nv_bfloat162 t = __floats2bfloat162_rn(a, b);
    return *(uint32_t*)&t;
}

// ---------------------------------------------------------------------------
// fp32 -> bf16 hi/lo split (elementwise)
// ---------------------------------------------------------------------------
__global__ __launch_bounds__(256) void convert_hl(
    const float* __restrict__ src, __nv_bfloat16* __restrict__ hi,
    __nv_bfloat16* __restrict__ lo, int n)
{
    int i = (blockIdx.x * blockDim.x + threadIdx.x) * 4;
    if (i >= n) return;
    float4 v = *(const float4*)(src + i);
    float f[4] = {v.x, v.y, v.z, v.w};
    __nv_bfloat16 h[4], l[4];
#pragma unroll
    for (int j = 0; j < 4; ++j) {
        h[j] = __float2bfloat16(f[j]);
        l[j] = __float2bfloat16(f[j] - __bfloat162float(h[j]));
    }
    *(uint2*)(hi + i) = *(uint2*)h;
    *(uint2*)(lo + i) = *(uint2*)l;
}

// ---------------------------------------------------------------------------
// W[k][n] -> Wt[n][k] bf16 hi/lo (tiled transpose), grid.z = section 0..3
// ---------------------------------------------------------------------------
__global__ __launch_bounds__(256) void convert_w4_t(
    const float* __restrict__ W0, const float* __restrict__ W1,
    const float* __restrict__ W2, const float* __restrict__ W3)
{
    __shared__ float t[32][33];
    const int sec = blockIdx.z;
    const float* W = (sec == 0) ? W0 : (sec == 1) ? W1 : (sec == 2) ? W2 : W3;
    __nv_bfloat16* hi = g_whi + (size_t)sec * DD * DD;
    __nv_bfloat16* lo = g_wlo + (size_t)sec * DD * DD;
    int tx = threadIdx.x, ty = threadIdx.y;
    int kin = blockIdx.y * 32;
    int nin = blockIdx.x * 32;
#pragma unroll
    for (int j = 0; j < 4; ++j)
        t[ty + j * 8][tx] = W[(size_t)(kin + ty + j * 8) * DD + nin + tx];
    __syncthreads();
#pragma unroll
    for (int j = 0; j < 4; ++j) {
        float v = t[tx][ty + j * 8];
        __nv_bfloat16 h = __float2bfloat16(v);
        __nv_bfloat16 l = __float2bfloat16(v - __bfloat162float(h));
        size_t o = (size_t)(nin + ty + j * 8) * DD + kin + tx;
        hi[o] = h;
        lo[o] = l;
    }
}

// ---------------------------------------------------------------------------
// bf16x3 HMMA GEMM (exact R10 main loop): CTA 128x128, 8 warps (64x32 each),
// BK=32, scalar LDS fragments, cp.async double buffer, 2 CTAs/SM.
// QKV=true: fused N=3072; epilogue by section:
//   sec 0/1 -> RoPE rotate + bf16 hi/lo Q/K [b,h,s,dk]; sec 2 -> bf16 hi/lo V^T.
// QKV=false: fp32 out [m][n] + bias.
// ---------------------------------------------------------------------------
#define GEMM_SMEM 81920

template <bool QKV>
__global__ __launch_bounds__(256, 2) void mma_gemm(
    const __nv_bfloat16* __restrict__ Ahi, const __nv_bfloat16* __restrict__ Alo,
    const __nv_bfloat16* __restrict__ Bhi, const __nv_bfloat16* __restrict__ Blo,
    const float* __restrict__ b0p, const float* __restrict__ b1p,
    const float* __restrict__ b2p,
    const int* __restrict__ pos, float* __restrict__ out)
{
    extern __shared__ char smem[];
    const uint32_t smem_u = s2u(smem);
    const int tid = threadIdx.x;
    const int lane = tid & 31;
    const int wid = tid >> 5;
    const int g = lane >> 2;
    const int tg = lane & 3;
    const int warp_m = wid & 1;
    const int warp_n = wid >> 1;
    const int n0 = blockIdx.x * 128;
    const int m0 = blockIdx.y * 128;

    float acc[4][4][4] = {};

    const int r_ = tid >> 2, c4 = tid & 3;

    auto load_stage = [&](int st, int kc) {
        const int k0 = kc * 32;
        const uint32_t sb = smem_u + st * 40960;
        {
            uint32_t d = sb + r_ * 80 + c4 * 16;
            size_t gsrc = (size_t)(m0 + r_) * DD + k0 + c4 * 8;
            cp16(d, Ahi + gsrc);
            cp16(d + 10240, Alo + gsrc);
            d += 64 * 80;  gsrc += (size_t)64 * DD;
            cp16(d, Ahi + gsrc);
            cp16(d + 10240, Alo + gsrc);
        }
        {
            uint32_t d = sb + 20480 + r_ * 80 + c4 * 16;
            size_t gsrc = (size_t)(n0 + r_) * DD + k0 + c4 * 8;
            cp16(d, Bhi + gsrc);
            cp16(d + 10240, Blo + gsrc);
            d += 64 * 80;  gsrc += (size_t)64 * DD;
            cp16(d, Bhi + gsrc);
            cp16(d + 10240, Blo + gsrc);
        }
    };

    load_stage(0, 0); CP_COMMIT();
    load_stage(1, 1); CP_COMMIT();

    for (int kc = 0; kc < 32; ++kc) {
        const int st = kc & 1;
        CP_WAIT1();
        __syncthreads();

        const char* sA = smem + st * 40960 + (warp_m * 64) * 80;
        const char* sB = smem + st * 40960 + 20480 + (warp_n * 32) * 80;

#pragma unroll
        for (int ks = 0; ks < 2; ++ks) {
            const int kb = ks * 32 + tg * 4;

            uint32_t bh[4][2], ah[4][4];
#pragma unroll
            for (int nt = 0; nt < 4; ++nt) {
                const char* p = sB + (nt * 8 + g) * 80 + kb;
                bh[nt][0] = *(const uint32_t*)p;
                bh[nt][1] = *(const uint32_t*)(p + 16);
            }
#pragma unroll
            for (int mt = 0; mt < 4; ++mt) {
                const char* p = sA + (mt * 16 + g) * 80 + kb;
                ah[mt][0] = *(const uint32_t*)p;
                ah[mt][1] = *(const uint32_t*)(p + 640);
                ah[mt][2] = *(const uint32_t*)(p + 16);
                ah[mt][3] = *(const uint32_t*)(p + 656);
            }
#pragma unroll
            for (int mt = 0; mt < 4; ++mt)
#pragma unroll
                for (int nt = 0; nt < 4; ++nt)
                    mma16816(acc[mt][nt], ah[mt], bh[nt]);

            uint32_t bl[4][2];
#pragma unroll
            for (int nt = 0; nt < 4; ++nt) {
                const char* p = sB + 10240 + (nt * 8 + g) * 80 + kb;
                bl[nt][0] = *(const uint32_t*)p;
                bl[nt][1] = *(const uint32_t*)(p + 16);
            }
#pragma unroll
            for (int mt = 0; mt < 4; ++mt)
#pragma unroll
                for (int nt = 0; nt < 4; ++nt)
                    mma16816(acc[mt][nt], ah[mt], bl[nt]);

            uint32_t al[4][4];
#pragma unroll
            for (int mt = 0; mt < 4; ++mt) {
                const char* p = sA + 10240 + (mt * 16 + g) * 80 + kb;
                al[mt][0] = *(const uint32_t*)p;
                al[mt][1] = *(const uint32_t*)(p + 640);
                al[mt][2] = *(const uint32_t*)(p + 16);
                al[mt][3] = *(const uint32_t*)(p + 656);
            }
#pragma unroll
            for (int mt = 0; mt < 4; ++mt)
#pragma unroll
                for (int nt = 0; nt < 4; ++nt)
                    mma16816(acc[mt][nt], al[mt], bh[nt]);
        }

        __syncthreads();
        if (kc + 2 < 32) load_stage(st, kc + 2);
        CP_COMMIT();
    }

    // ---- epilogue ----
    const int sec = QKV ? (n0 >> 10) : 0;   // uniform per CTA
    const float* bias = QKV ? ((sec == 0) ? b0p : (sec == 1) ? b1p : b2p) : b0p;

    int pv[4][2];
    if (QKV && sec < 2) {
#pragma unroll
        for (int mt = 0; mt < 4; ++mt) {
            const int m = m0 + warp_m * 64 + mt * 16 + g;
            const int b_ = m >> 11, s = m & 2047;
            pv[mt][0] = pos[b_ * SS + s];
            pv[mt][1] = pos[b_ * SS + s + 8];
        }
    }

#pragma unroll
    for (int nt = 0; nt < 4; ++nt) {
        const int nc = n0 + warp_n * 32 + nt * 8 + tg * 2;
        const int nl = QKV ? (nc & 1023) : nc;
        const int hh = nl >> 6, dk = nl & 63;
        const float bv0 = __ldg(bias + nl), bv1 = __ldg(bias + nl + 1);

        float invf = 0.f;
        if (QKV && sec < 2)
            invf = (float)exp(-(double)(dk >> 1) * 0.28782313662425575);

#pragma unroll
        for (int mt = 0; mt < 4; ++mt) {
            const int m = m0 + warp_m * 64 + mt * 16 + g;
            float v00 = acc[mt][nt][0] + bv0, v01 = acc[mt][nt][1] + bv1;
            float v10 = acc[mt][nt][2] + bv0, v11 = acc[mt][nt][3] + bv1;

            if (!QKV) {
                *(float2*)(out + (size_t)m * DD + nc) = make_float2(v00, v01);
                *(float2*)(out + (size_t)(m + 8) * DD + nc) = make_float2(v10, v11);
                continue;
            }

            const int b_ = m >> 11, s = m & 2047;
            if (sec < 2) {
                // RoPE rotate pairs, write bf16 hi/lo [b,h,s,dk]
                float cs, sn;
                sincosf((float)pv[mt][0] * invf, &sn, &cs);
                float r00 = v00 * cs - v01 * sn;
                float r01 = v00 * sn + v01 * cs;
                sincosf((float)pv[mt][1] * invf, &sn, &cs);
                float r10 = v10 * cs - v11 * sn;
                float r11 = v10 * sn + v11 * cs;

                __nv_bfloat16* Hi = (sec == 0) ? g_Qhi : g_Khi;
                __nv_bfloat16* Lo = (sec == 0) ? g_Qlo : g_Klo;
                size_t base = (((size_t)(b_ * HH + hh) * SS) + s) * DKK + dk;
                uint32_t h2 = pack_bf2(r00, r01);
                *(uint32_t*)(Hi + base) = h2;
                __nv_bfloat162 hv = *(__nv_bfloat162*)&h2;
                *(uint32_t*)(Lo + base) =
                    pack_bf2(r00 - __bfloat162float(hv.x), r01 - __bfloat162float(hv.y));
                h2 = pack_bf2(r10, r11);
                *(uint32_t*)(Hi + base + 8 * DKK) = h2;
                hv = *(__nv_bfloat162*)&h2;
                *(uint32_t*)(Lo + base + 8 * DKK) =
                    pack_bf2(r10 - __bfloat162float(hv.x), r11 - __bfloat162float(hv.y));
            } else {
                // V: bf16 hi/lo transposed [b,h,dk,s]
                size_t base = (((size_t)(b_ * HH + hh) * DKK) + dk) * SS + s;
                float vv[4] = {v00, v01, v10, v11};
                size_t off[4] = {base, base + SS, base + 8, base + SS + 8};
#pragma unroll
                for (int e = 0; e < 4; ++e) {
                    __nv_bfloat16 hb = __float2bfloat16(vv[e]);
                    g_Vthi[off[e]] = hb;
                    g_Vtlo[off[e]] = __float2bfloat16(vv[e] - __bfloat162float(hb));
                }
            }
        }
    }
}

// ---------------------------------------------------------------------------
// Flash attention with HMMA (bf16x3). CTA = 128 q-rows of one (b,h);
// 256 threads, 8 warps of 16 rows. K/V 64-key stages double-buffered —
// each stage now feeds 2x the q-rows (halved K/V traffic vs 64-row tiles).
// ---------------------------------------------------------------------------
#define FL_PITCH 144
#define FL_TILE (64 * FL_PITCH)
#define FL_STAGE (4 * FL_TILE)
#define FL_SMEM (2 * FL_STAGE)

__global__ __launch_bounds__(256) void flash_mma()
{
    extern __shared__ char smem[];
    const int qt = (int)gridDim.x - 1 - (int)blockIdx.x;  // heavy first
    const int h = blockIdx.y;
    const int b = blockIdx.z;
    const int q0 = qt * 128;
    const int tid = threadIdx.x;
    const int lane = tid & 31;
    const int w = tid >> 5;        // 0..7
    const int g = lane >> 2;
    const int tg = lane & 3;

    const size_t bh = (size_t)(b * HH + h);
    const __nv_bfloat16* Qhi = g_Qhi + bh * SS * DKK;
    const __nv_bfloat16* Qlo = g_Qlo + bh * SS * DKK;
    const __nv_bfloat16* Khi = g_Khi + bh * SS * DKK;
    const __nv_bfloat16* Klo = g_Klo + bh * SS * DKK;
    const __nv_bfloat16* Vthi = g_Vthi + bh * DKK * SS;
    const __nv_bfloat16* Vtlo = g_Vtlo + bh * DKK * SS;

    const int qrow = q0 + w * 16 + g;
    uint32_t qh[4][4], ql[4][4];
#pragma unroll
    for (int kc = 0; kc < 4; ++kc) {
        size_t p0 = (size_t)qrow * DKK + kc * 16 + tg * 2;
        qh[kc][0] = *(const uint32_t*)(Qhi + p0);
        qh[kc][1] = *(const uint32_t*)(Qhi + p0 + 8 * DKK);
        qh[kc][2] = *(const uint32_t*)(Qhi + p0 + 8);
        qh[kc][3] = *(const uint32_t*)(Qhi + p0 + 8 * DKK + 8);
        ql[kc][0] = *(const uint32_t*)(Qlo + p0);
        ql[kc][1] = *(const uint32_t*)(Qlo + p0 + 8 * DKK);
        ql[kc][2] = *(const uint32_t*)(Qlo + p0 + 8);
        ql[kc][3] = *(const uint32_t*)(Qlo + p0 + 8 * DKK + 8);
    }

    auto load_stage = [&](int st, int t) {
        const int j0 = t * 64;
        char* sb = smem + st * FL_STAGE;
#pragma unroll
        for (int i = 0; i < 2; ++i) {
            int v = i * 256 + tid;
            int r = v >> 3, c = v & 7;
            uint32_t d = s2u(sb + r * FL_PITCH + c * 16);
            size_t ksrc = (size_t)(j0 + r) * DKK + c * 8;
            cp16(d, Khi + ksrc);
            cp16(d + FL_TILE, Klo + ksrc);
            size_t vsrc = (size_t)r * SS + j0 + c * 8;
            cp16(d + 2 * FL_TILE, Vthi + vsrc);
            cp16(d + 3 * FL_TILE, Vtlo + vsrc);
        }
    };

    float o[8][4] = {};
    float m_g = -1e30f, m_g8 = -1e30f;
    float l_g = 0.f, l_g8 = 0.f;

    const int nT = 2 * qt + 2;
    load_stage(0, 0); CP_COMMIT();
    load_stage(1, 1); CP_COMMIT();

    for (int t = 0; t < nT; ++t) {
        const int st = t & 1;
        CP_WAIT1();
        __syncthreads();

        const char* sK  = smem + st * FL_STAGE;
        const char* sKl = sK + FL_TILE;
        const char* sV  = sK + 2 * FL_TILE;
        const char* sVl = sK + 3 * FL_TILE;
        const int j0 = t * 64;

        float s[8][4] = {};
#pragma unroll
        for (int kc = 0; kc < 4; ++kc) {
            const int kb = kc * 32 + tg * 4;
            uint32_t kh[8][2], kl[8][2];
#pragma unroll
            for (int nf = 0; nf < 8; ++nf) {
                const char* p = sK + (nf * 8 + g) * FL_PITCH + kb;
                kh[nf][0] = *(const uint32_t*)p;
                kh[nf][1] = *(const uint32_t*)(p + 16);
                const char* p2 = sKl + (nf * 8 + g) * FL_PITCH + kb;
                kl[nf][0] = *(const uint32_t*)p2;
                kl[nf][1] = *(const uint32_t*)(p2 + 16);
            }
#pragma unroll
            for (int nf = 0; nf < 8; ++nf) {
                mma16816(s[nf], qh[kc], kh[nf]);
                mma16816(s[nf], qh[kc], kl[nf]);
                mma16816(s[nf], ql[kc], kh[nf]);
            }
        }

        // causal mask needed only on the last two tiles (keys >= q0)
        const bool diag = (t >= nT - 2);
#pragma unroll
        for (int nf = 0; nf < 8; ++nf) {
#pragma unroll
            for (int e = 0; e < 4; ++e) {
                float v = s[nf][e] * SCALE;
                if (diag) {
                    int col = j0 + nf * 8 + tg * 2 + (e & 1);
                    int row = qrow + ((e >> 1) << 3);
                    if (col > row) v = -1e30f;
                }
                s[nf][e] = v;
            }
        }

        float tm_g = -1e30f, tm_g8 = -1e30f;
#pragma unroll
        for (int nf = 0; nf < 8; ++nf) {
            tm_g  = fmaxf(tm_g,  fmaxf(s[nf][0], s[nf][1]));
            tm_g8 = fmaxf(tm_g8, fmaxf(s[nf][2], s[nf][3]));
        }
        tm_g  = fmaxf(tm_g,  __shfl_xor_sync(0xffffffffu, tm_g, 1));
        tm_g  = fmaxf(tm_g,  __shfl_xor_sync(0xffffffffu, tm_g, 2));
        tm_g8 = fmaxf(tm_g8, __shfl_xor_sync(0xffffffffu, tm_g8, 1));
        tm_g8 = fmaxf(tm_g8, __shfl_xor_sync(0xffffffffu, tm_g8, 2));

        float mn_g = fmaxf(m_g, tm_g);
        float mn_g8 = fmaxf(m_g8, tm_g8);
        float alpha_g = expf(m_g - mn_g);
        float alpha_g8 = expf(m_g8 - mn_g8);
        m_g = mn_g; m_g8 = mn_g8;

        float sum_g = 0.f, sum_g8 = 0.f;
#pragma unroll
        for (int nf = 0; nf < 8; ++nf) {
            s[nf][0] = expf(s[nf][0] - mn_g);
            s[nf][1] = expf(s[nf][1] - mn_g);
            s[nf][2] = expf(s[nf][2] - mn_g8);
            s[nf][3] = expf(s[nf][3] - mn_g8);
            sum_g += s[nf][0] + s[nf][1];
            sum_g8 += s[nf][2] + s[nf][3];
        }
        sum_g  += __shfl_xor_sync(0xffffffffu, sum_g, 1);
        sum_g  += __shfl_xor_sync(0xffffffffu, sum_g, 2);
        sum_g8 += __shfl_xor_sync(0xffffffffu, sum_g8, 1);
        sum_g8 += __shfl_xor_sync(0xffffffffu, sum_g8, 2);
        l_g = l_g * alpha_g + sum_g;
        l_g8 = l_g8 * alpha_g8 + sum_g8;

#pragma unroll
        for (int nf = 0; nf < 8; ++nf) {
            o[nf][0] *= alpha_g;
            o[nf][1] *= alpha_g;
            o[nf][2] *= alpha_g8;
            o[nf][3] *= alpha_g8;
        }

#pragma unroll
        for (int kc = 0; kc < 4; ++kc) {
            uint32_t ph[4], pl[4];
            {
                const float* s0 = s[2 * kc];
                const float* s1 = s[2 * kc + 1];
                float h0 = __bfloat162float(__float2bfloat16(s0[0]));
                float h1 = __bfloat162float(__float2bfloat16(s0[1]));
                float h2 = __bfloat162float(__float2bfloat16(s0[2]));
                float h3 = __bfloat162float(__float2bfloat16(s0[3]));
                float h4 = __bfloat162float(__float2bfloat16(s1[0]));
                float h5 = __bfloat162float(__float2bfloat16(s1[1]));
                float h6 = __bfloat162float(__float2bfloat16(s1[2]));
                float h7 = __bfloat162float(__float2bfloat16(s1[3]));
                ph[0] = pack_bf2(h0, h1);
                ph[1] = pack_bf2(h2, h3);
                ph[2] = pack_bf2(h4, h5);
                ph[3] = pack_bf2(h6, h7);
                pl[0] = pack_bf2(s0[0] - h0, s0[1] - h1);
                pl[1] = pack_bf2(s0[2] - h2, s0[3] - h3);
                pl[2] = pack_bf2(s1[0] - h4, s1[1] - h5);
                pl[3] = pack_bf2(s1[2] - h6, s1[3] - h7);
            }
            const int kb = kc * 32 + tg * 4;
            uint32_t vh[8][2], vl[8][2];
#pragma unroll
            for (int nf = 0; nf < 8; ++nf) {
                const char* p = sV + (nf * 8 + g) * FL_PITCH + kb;
                vh[nf][0] = *(const uint32_t*)p;
                vh[nf][1] = *(const uint32_t*)(p + 16);
                const char* p2 = sVl + (nf * 8 + g) * FL_PITCH + kb;
                vl[nf][0] = *(const uint32_t*)p2;
                vl[nf][1] = *(const uint32_t*)(p2 + 16);
            }
#pragma unroll
            for (int nf = 0; nf < 8; ++nf) {
                mma16816(o[nf], ph, vh[nf]);
                mma16816(o[nf], ph, vl[nf]);
                mma16816(o[nf], pl, vh[nf]);
            }
        }

        __syncthreads();
        if (t + 2 < nT) load_stage(st, t + 2);
        CP_COMMIT();
    }

    const float inv_g = 1.0f / l_g;
    const float inv_g8 = 1.0f / l_g8;
#pragma unroll
    for (int nf = 0; nf < 8; ++nf) {
        const int col = h * DKK + nf * 8 + tg * 2;
        {
            float v0 = o[nf][0] * inv_g, v1 = o[nf][1] * inv_g;
            size_t addr = ((size_t)b * SS + qrow) * DD + col;
            __nv_bfloat162 hh = __floats2bfloat162_rn(v0, v1);
            *(uint32_t*)(g_ahi + addr) = *(uint32_t*)&hh;
            __nv_bfloat162 ll = __floats2bfloat162_rn(v0 - __bfloat162float(hh.x),
                                                      v1 - __bfloat162float(hh.y));
            *(uint32_t*)(g_alo + addr) = *(uint32_t*)&ll;
        }
        {
            float v0 = o[nf][2] * inv_g8, v1 = o[nf][3] * inv_g8;
            size_t addr = ((size_t)b * SS + qrow + 8) * DD + col;
            __nv_bfloat162 hh = __floats2bfloat162_rn(v0, v1);
            *(uint32_t*)(g_ahi + addr) = *(uint32_t*)&hh;
            __nv_bfloat162 ll = __floats2bfloat162_rn(v0 - __bfloat162float(hh.x),
                                                      v1 - __bfloat162float(hh.y));
            *(uint32_t*)(g_alo + addr) = *(uint32_t*)&ll;
        }
    }
}

// ---------------------------------------------------------------------------
extern "C" void kernel_launch(void* const* d_in, const int* in_sizes, int n_in,
                              void* d_out, int out_size)
{
    const float* x  = (const float*)d_in[0];
    const int*   tp = (const int*)d_in[1];
    const float* Wq = (const float*)d_in[2];
    const float* bq = (const float*)d_in[3];
    const float* Wk = (const float*)d_in[4];
    const float* bk = (const float*)d_in[5];
    const float* Wv = (const float*)d_in[6];
    const float* bv = (const float*)d_in[7];
    const float* Wo = (const float*)d_in[8];
    const float* bo = (const float*)d_in[9];
    float* out = (float*)d_out;

    __nv_bfloat16 *xhi, *xlo, *ahi, *alo, *whi, *wlo;
    cudaGetSymbolAddress((void**)&xhi, g_xhi);
    cudaGetSymbolAddress((void**)&xlo, g_xlo);
    cudaGetSymbolAddress((void**)&ahi, g_ahi);
    cudaGetSymbolAddress((void**)&alo, g_alo);
    cudaGetSymbolAddress((void**)&whi, g_whi);
    cudaGetSymbolAddress((void**)&wlo, g_wlo);

    static int attr_set = 0;
    if (!attr_set) {
        cudaFuncSetAttribute(mma_gemm<true>,
                             cudaFuncAttributeMaxDynamicSharedMemorySize, GEMM_SMEM);
        cudaFuncSetAttribute(mma_gemm<false>,
                             cudaFuncAttributeMaxDynamicSharedMemorySize, GEMM_SMEM);
        cudaFuncSetAttribute(flash_mma,
                             cudaFuncAttributeMaxDynamicSharedMemorySize, FL_SMEM);
        attr_set = 1;
    }

    const int nX = MM * DD;
    dim3 bW(32, 8);

    convert_hl<<<nX / 4 / 256, 256>>>(x, xhi, xlo, nX);
    convert_w4_t<<<dim3(32, 32, 4), bW>>>(Wq, Wk, Wv, Wo);

    // Fused QKV projection with RoPE epilogue: N=3072, 768 CTAs
    dim3 gQKV(3 * DD / 128, MM / 128);  // (24, 32)
    mma_gemm<true><<<gQKV, 256, GEMM_SMEM>>>(xhi, xlo, whi, wlo,
                                             bq, bk, bv, tp, nullptr);

    // Flash attention: 128-row q-tiles, 512 CTAs
    dim3 gFlash(SS / 128, HH, BB);  // (16, 16, 2)
    flash_mma<<<gFlash, 256, FL_SMEM>>>();

    // O projection (weight section 3)
    dim3 gO(DD / 128, MM / 128);  // (8, 32)
    mma_gemm<false><<<gO, 256, GEMM_SMEM>>>(ahi, alo,
                                            whi + (size_t)3 * DD * DD,
                                            wlo + (size_t)3 * DD * DD,
                                            bo, bo, bo, tp, out);
}

// round 17
// speedup vs baseline: 1.1026x; 1.1026x over previous
#include <cuda_runtime.h>
#include <cuda_bf16.h>
#include <math.h>
#include <stdint.h>

// Problem constants
#define BB 2
#define SS 2048
#define DD 1024
#define HH 16
#define DKK 64
#define MM (BB * SS)          // 4096
#define SCALE 0.125f          // 1/sqrt(64)

// Scratch (allocation-free rule: __device__ globals)
__device__ __nv_bfloat16 g_Qhi[BB * HH * SS * DKK];  // post-RoPE hi/lo
__device__ __nv_bfloat16 g_Qlo[BB * HH * SS * DKK];
__device__ __nv_bfloat16 g_Khi[BB * HH * SS * DKK];
__device__ __nv_bfloat16 g_Klo[BB * HH * SS * DKK];
__device__ __nv_bfloat16 g_Vthi[BB * HH * DKK * SS]; // V transposed [b,h,dk,s]
__device__ __nv_bfloat16 g_Vtlo[BB * HH * DKK * SS];
__device__ __nv_bfloat16 g_xhi[MM * DD];
__device__ __nv_bfloat16 g_xlo[MM * DD];
__device__ __nv_bfloat16 g_ahi[MM * DD];    // attention output hi/lo (O-proj input)
__device__ __nv_bfloat16 g_alo[MM * DD];
__device__ __nv_bfloat16 g_whi[4 * DD * DD]; // W^T hi: secs 0..2 = QKV, 3 = O
__device__ __nv_bfloat16 g_wlo[4 * DD * DD];

// ---------------------------------------------------------------------------
// Helpers
// ---------------------------------------------------------------------------
__device__ __forceinline__ uint32_t s2u(const void* p) {
    uint32_t a;
    asm("{ .reg .u64 t; cvta.to.shared.u64 t, %1; cvt.u32.u64 %0, t; }"
        : "=r"(a) : "l"(p));
    return a;
}
__device__ __forceinline__ void cp16(uint32_t dst, const void* src) {
    asm volatile("cp.async.cg.shared.global [%0], [%1], 16;" :: "r"(dst), "l"(src));
}
#define CP_COMMIT() asm volatile("cp.async.commit_group;" ::: "memory")
#define CP_WAIT1()  asm volatile("cp.async.wait_group 1;" ::: "memory")

__device__ __forceinline__ void mma16816(float* c, const uint32_t* a, const uint32_t* b)
{
    asm volatile(
        "mma.sync.aligned.m16n8k16.row.col.f32.bf16.bf16.f32 "
        "{%0,%1,%2,%3}, {%4,%5,%6,%7}, {%8,%9}, {%0,%1,%2,%3};"
        : "+f"(c[0]), "+f"(c[1]), "+f"(c[2]), "+f"(c[3])
        : "r"(a[0]), "r"(a[1]), "r"(a[2]), "r"(a[3]), "r"(b[0]), "r"(b[1]));
}
__device__ __forceinline__ uint32_t pack_bf2(float a, float b) {
    __nv_bfloat162 t = __floats2bfloat162_rn(a, b);
    return *(uint32_t*)&t;
}

// ---------------------------------------------------------------------------
// fp32 -> bf16 hi/lo split (elementwise)
// ---------------------------------------------------------------------------
__global__ __launch_bounds__(256) void convert_hl(
    const float* __restrict__ src, __nv_bfloat16* __restrict__ hi,
    __nv_bfloat16* __restrict__ lo, int n)
{
    int i = (blockIdx.x * blockDim.x + threadIdx.x) * 4;
    if (i >= n) return;
    float4 v = *(const float4*)(src + i);
    float f[4] = {v.x, v.y, v.z, v.w};
    __nv_bfloat16 h[4], l[4];
#pragma unroll
    for (int j = 0; j < 4; ++j) {
        h[j] = __float2bfloat16(f[j]);
        l[j] = __float2bfloat16(f[j] - __bfloat162float(h[j]));
    }
    *(uint2*)(hi + i) = *(uint2*)h;
    *(uint2*)(lo + i) = *(uint2*)l;
}

// ---------------------------------------------------------------------------
// W[k][n] -> Wt[n][k] bf16 hi/lo (tiled transpose), grid.z = section 0..3
// ---------------------------------------------------------------------------
__global__ __launch_bounds__(256) void convert_w4_t(
    const float* __restrict__ W0, const float* __restrict__ W1,
    const float* __restrict__ W2, const float* __restrict__ W3)
{
    __shared__ float t[32][33];
    const int sec = blockIdx.z;
    const float* W = (sec == 0) ? W0 : (sec == 1) ? W1 : (sec == 2) ? W2 : W3;
    __nv_bfloat16* hi = g_whi + (size_t)sec * DD * DD;
    __nv_bfloat16* lo = g_wlo + (size_t)sec * DD * DD;
    int tx = threadIdx.x, ty = threadIdx.y;
    int kin = blockIdx.y * 32;
    int nin = blockIdx.x * 32;
#pragma unroll
    for (int j = 0; j < 4; ++j)
        t[ty + j * 8][tx] = W[(size_t)(kin + ty + j * 8) * DD + nin + tx];
    __syncthreads();
#pragma unroll
    for (int j = 0; j < 4; ++j) {
        float v = t[tx][ty + j * 8];
        __nv_bfloat16 h = __float2bfloat16(v);
        __nv_bfloat16 l = __float2bfloat16(v - __bfloat162float(h));
        size_t o = (size_t)(nin + ty + j * 8) * DD + kin + tx;
        hi[o] = h;
        lo[o] = l;
    }
}

// ---------------------------------------------------------------------------
// bf16x3 HMMA GEMM (exact R10 main loop): CTA 128x128, 8 warps (64x32 each),
// BK=32, scalar LDS fragments, cp.async double buffer, 2 CTAs/SM.
// QKV=true: fused N=3072; epilogue by section:
//   sec 0/1 -> RoPE rotate + bf16 hi/lo Q/K [b,h,s,dk]; sec 2 -> bf16 hi/lo V^T.
// QKV=false: fp32 out [m][n] + bias.
// ---------------------------------------------------------------------------
#define GEMM_SMEM 81920

template <bool QKV>
__global__ __launch_bounds__(256, 2) void mma_gemm(
    const __nv_bfloat16* __restrict__ Ahi, const __nv_bfloat16* __restrict__ Alo,
    const __nv_bfloat16* __restrict__ Bhi, const __nv_bfloat16* __restrict__ Blo,
    const float* __restrict__ b0p, const float* __restrict__ b1p,
    const float* __restrict__ b2p,
    const int* __restrict__ pos, float* __restrict__ out)
{
    extern __shared__ char smem[];
    const uint32_t smem_u = s2u(smem);
    const int tid = threadIdx.x;
    const int lane = tid & 31;
    const int wid = tid >> 5;
    const int g = lane >> 2;
    const int tg = lane & 3;
    const int warp_m = wid & 1;
    const int warp_n = wid >> 1;
    const int n0 = blockIdx.x * 128;
    const int m0 = blockIdx.y * 128;

    float acc[4][4][4] = {};

    const int r_ = tid >> 2, c4 = tid & 3;

    auto load_stage = [&](int st, int kc) {
        const int k0 = kc * 32;
        const uint32_t sb = smem_u + st * 40960;
        {
            uint32_t d = sb + r_ * 80 + c4 * 16;
            size_t gsrc = (size_t)(m0 + r_) * DD + k0 + c4 * 8;
            cp16(d, Ahi + gsrc);
            cp16(d + 10240, Alo + gsrc);
            d += 64 * 80;  gsrc += (size_t)64 * DD;
            cp16(d, Ahi + gsrc);
            cp16(d + 10240, Alo + gsrc);
        }
        {
            uint32_t d = sb + 20480 + r_ * 80 + c4 * 16;
            size_t gsrc = (size_t)(n0 + r_) * DD + k0 + c4 * 8;
            cp16(d, Bhi + gsrc);
            cp16(d + 10240, Blo + gsrc);
            d += 64 * 80;  gsrc += (size_t)64 * DD;
            cp16(d, Bhi + gsrc);
            cp16(d + 10240, Blo + gsrc);
        }
    };

    load_stage(0, 0); CP_COMMIT();
    load_stage(1, 1); CP_COMMIT();

    for (int kc = 0; kc < 32; ++kc) {
        const int st = kc & 1;
        CP_WAIT1();
        __syncthreads();

        const char* sA = smem + st * 40960 + (warp_m * 64) * 80;
        const char* sB = smem + st * 40960 + 20480 + (warp_n * 32) * 80;

#pragma unroll
        for (int ks = 0; ks < 2; ++ks) {
            const int kb = ks * 32 + tg * 4;

            uint32_t bh[4][2], ah[4][4];
#pragma unroll
            for (int nt = 0; nt < 4; ++nt) {
                const char* p = sB + (nt * 8 + g) * 80 + kb;
                bh[nt][0] = *(const uint32_t*)p;
                bh[nt][1] = *(const uint32_t*)(p + 16);
            }
#pragma unroll
            for (int mt = 0; mt < 4; ++mt) {
                const char* p = sA + (mt * 16 + g) * 80 + kb;
                ah[mt][0] = *(const uint32_t*)p;
                ah[mt][1] = *(const uint32_t*)(p + 640);
                ah[mt][2] = *(const uint32_t*)(p + 16);
                ah[mt][3] = *(const uint32_t*)(p + 656);
            }
#pragma unroll
            for (int mt = 0; mt < 4; ++mt)
#pragma unroll
                for (int nt = 0; nt < 4; ++nt)
                    mma16816(acc[mt][nt], ah[mt], bh[nt]);

            uint32_t bl[4][2];
#pragma unroll
            for (int nt = 0; nt < 4; ++nt) {
                const char* p = sB + 10240 + (nt * 8 + g) * 80 + kb;
                bl[nt][0] = *(const uint32_t*)p;
                bl[nt][1] = *(const uint32_t*)(p + 16);
            }
#pragma unroll
            for (int mt = 0; mt < 4; ++mt)
#pragma unroll
                for (int nt = 0; nt < 4; ++nt)
                    mma16816(acc[mt][nt], ah[mt], bl[nt]);

            uint32_t al[4][4];
#pragma unroll
            for (int mt = 0; mt < 4; ++mt) {
                const char* p = sA + 10240 + (mt * 16 + g) * 80 + kb;
                al[mt][0] = *(const uint32_t*)p;
                al[mt][1] = *(const uint32_t*)(p + 640);
                al[mt][2] = *(const uint32_t*)(p + 16);
                al[mt][3] = *(const uint32_t*)(p + 656);
            }
#pragma unroll
            for (int mt = 0; mt < 4; ++mt)
#pragma unroll
                for (int nt = 0; nt < 4; ++nt)
                    mma16816(acc[mt][nt], al[mt], bh[nt]);
        }

        __syncthreads();
        if (kc + 2 < 32) load_stage(st, kc + 2);
        CP_COMMIT();
    }

    // ---- epilogue ----
    const int sec = QKV ? (n0 >> 10) : 0;   // uniform per CTA
    const float* bias = QKV ? ((sec == 0) ? b0p : (sec == 1) ? b1p : b2p) : b0p;

    int pv[4][2];
    if (QKV && sec < 2) {
#pragma unroll
        for (int mt = 0; mt < 4; ++mt) {
            const int m = m0 + warp_m * 64 + mt * 16 + g;
            const int b_ = m >> 11, s = m & 2047;
            pv[mt][0] = pos[b_ * SS + s];
            pv[mt][1] = pos[b_ * SS + s + 8];
        }
    }

#pragma unroll
    for (int nt = 0; nt < 4; ++nt) {
        const int nc = n0 + warp_n * 32 + nt * 8 + tg * 2;
        const int nl = QKV ? (nc & 1023) : nc;
        const int hh = nl >> 6, dk = nl & 63;
        const float bv0 = __ldg(bias + nl), bv1 = __ldg(bias + nl + 1);

        float invf = 0.f;
        if (QKV && sec < 2)
            invf = (float)exp(-(double)(dk >> 1) * 0.28782313662425575);

#pragma unroll
        for (int mt = 0; mt < 4; ++mt) {
            const int m = m0 + warp_m * 64 + mt * 16 + g;
            float v00 = acc[mt][nt][0] + bv0, v01 = acc[mt][nt][1] + bv1;
            float v10 = acc[mt][nt][2] + bv0, v11 = acc[mt][nt][3] + bv1;

            if (!QKV) {
                *(float2*)(out + (size_t)m * DD + nc) = make_float2(v00, v01);
                *(float2*)(out + (size_t)(m + 8) * DD + nc) = make_float2(v10, v11);
                continue;
            }

            const int b_ = m >> 11, s = m & 2047;
            if (sec < 2) {
                float cs, sn;
                sincosf((float)pv[mt][0] * invf, &sn, &cs);
                float r00 = v00 * cs - v01 * sn;
                float r01 = v00 * sn + v01 * cs;
                sincosf((float)pv[mt][1] * invf, &sn, &cs);
                float r10 = v10 * cs - v11 * sn;
                float r11 = v10 * sn + v11 * cs;

                __nv_bfloat16* Hi = (sec == 0) ? g_Qhi : g_Khi;
                __nv_bfloat16* Lo = (sec == 0) ? g_Qlo : g_Klo;
                size_t base = (((size_t)(b_ * HH + hh) * SS) + s) * DKK + dk;
                uint32_t h2 = pack_bf2(r00, r01);
                *(uint32_t*)(Hi + base) = h2;
                __nv_bfloat162 hv = *(__nv_bfloat162*)&h2;
                *(uint32_t*)(Lo + base) =
                    pack_bf2(r00 - __bfloat162float(hv.x), r01 - __bfloat162float(hv.y));
                h2 = pack_bf2(r10, r11);
                *(uint32_t*)(Hi + base + 8 * DKK) = h2;
                hv = *(__nv_bfloat162*)&h2;
                *(uint32_t*)(Lo + base + 8 * DKK) =
                    pack_bf2(r10 - __bfloat162float(hv.x), r11 - __bfloat162float(hv.y));
            } else {
                size_t base = (((size_t)(b_ * HH + hh) * DKK) + dk) * SS + s;
                float vv[4] = {v00, v01, v10, v11};
                size_t off[4] = {base, base + SS, base + 8, base + SS + 8};
#pragma unroll
                for (int e = 0; e < 4; ++e) {
                    __nv_bfloat16 hb = __float2bfloat16(vv[e]);
                    g_Vthi[off[e]] = hb;
                    g_Vtlo[off[e]] = __float2bfloat16(vv[e] - __bfloat162float(hb));
                }
            }
        }
    }
}

// ---------------------------------------------------------------------------
// Flash attention with HMMA (bf16x3). CTA = 64 q-rows of one (b,h);
// 128 threads, 4 warps of 16 rows. Double-buffered K/V stages.
// __launch_bounds__(128, 3): 3 CTAs/SM (regs 17.7K x3, smem 73728 x3 = 221KB).
// Output bf16 hi/lo into g_ahi/g_alo.
// ---------------------------------------------------------------------------
#define FL_PITCH 144
#define FL_TILE (64 * FL_PITCH)
#define FL_STAGE (4 * FL_TILE)
#define FL_SMEM (2 * FL_STAGE)

__global__ __launch_bounds__(128, 3) void flash_mma()
{
    extern __shared__ char smem[];
    const int qt = (int)gridDim.x - 1 - (int)blockIdx.x;  // heavy first
    const int h = blockIdx.y;
    const int b = blockIdx.z;
    const int q0 = qt * 64;
    const int tid = threadIdx.x;
    const int lane = tid & 31;
    const int w = tid >> 5;
    const int g = lane >> 2;
    const int tg = lane & 3;

    const size_t bh = (size_t)(b * HH + h);
    const __nv_bfloat16* Qhi = g_Qhi + bh * SS * DKK;
    const __nv_bfloat16* Qlo = g_Qlo + bh * SS * DKK;
    const __nv_bfloat16* Khi = g_Khi + bh * SS * DKK;
    const __nv_bfloat16* Klo = g_Klo + bh * SS * DKK;
    const __nv_bfloat16* Vthi = g_Vthi + bh * DKK * SS;
    const __nv_bfloat16* Vtlo = g_Vtlo + bh * DKK * SS;

    const int qrow = q0 + w * 16 + g;
    uint32_t qh[4][4], ql[4][4];
#pragma unroll
    for (int kc = 0; kc < 4; ++kc) {
        size_t p0 = (size_t)qrow * DKK + kc * 16 + tg * 2;
        qh[kc][0] = *(const uint32_t*)(Qhi + p0);
        qh[kc][1] = *(const uint32_t*)(Qhi + p0 + 8 * DKK);
        qh[kc][2] = *(const uint32_t*)(Qhi + p0 + 8);
        qh[kc][3] = *(const uint32_t*)(Qhi + p0 + 8 * DKK + 8);
        ql[kc][0] = *(const uint32_t*)(Qlo + p0);
        ql[kc][1] = *(const uint32_t*)(Qlo + p0 + 8 * DKK);
        ql[kc][2] = *(const uint32_t*)(Qlo + p0 + 8);
        ql[kc][3] = *(const uint32_t*)(Qlo + p0 + 8 * DKK + 8);
    }

    auto load_stage = [&](int st, int t) {
        const int j0 = t * 64;
        char* sb = smem + st * FL_STAGE;
#pragma unroll
        for (int i = 0; i < 4; ++i) {
            int v = i * 128 + tid;
            int r = v >> 3, c = v & 7;
            uint32_t d = s2u(sb + r * FL_PITCH + c * 16);
            size_t ksrc = (size_t)(j0 + r) * DKK + c * 8;
            cp16(d, Khi + ksrc);
            cp16(d + FL_TILE, Klo + ksrc);
            size_t vsrc = (size_t)r * SS + j0 + c * 8;
            cp16(d + 2 * FL_TILE, Vthi + vsrc);
            cp16(d + 3 * FL_TILE, Vtlo + vsrc);
        }
    };

    float o[8][4] = {};
    float m_g = -1e30f, m_g8 = -1e30f;
    float l_g = 0.f, l_g8 = 0.f;

    const int nT = qt + 1;
    load_stage(0, 0); CP_COMMIT();
    if (nT > 1) load_stage(1, 1);
    CP_COMMIT();

    for (int t = 0; t < nT; ++t) {
        const int st = t & 1;
        CP_WAIT1();
        __syncthreads();

        const char* sK  = smem + st * FL_STAGE;
        const char* sKl = sK + FL_TILE;
        const char* sV  = sK + 2 * FL_TILE;
        const char* sVl = sK + 3 * FL_TILE;
        const int j0 = t * 64;

        float s[8][4] = {};
#pragma unroll
        for (int kc = 0; kc < 4; ++kc) {
            const int kb = kc * 32 + tg * 4;
            uint32_t kh[8][2], kl[8][2];
#pragma unroll
            for (int nf = 0; nf < 8; ++nf) {
                const char* p = sK + (nf * 8 + g) * FL_PITCH + kb;
                kh[nf][0] = *(const uint32_t*)p;
                kh[nf][1] = *(const uint32_t*)(p + 16);
                const char* p2 = sKl + (nf * 8 + g) * FL_PITCH + kb;
                kl[nf][0] = *(const uint32_t*)p2;
                kl[nf][1] = *(const uint32_t*)(p2 + 16);
            }
#pragma unroll
            for (int nf = 0; nf < 8; ++nf) {
                mma16816(s[nf], qh[kc], kh[nf]);
                mma16816(s[nf], qh[kc], kl[nf]);
                mma16816(s[nf], ql[kc], kh[nf]);
            }
        }

        const bool diag = (t == qt);
#pragma unroll
        for (int nf = 0; nf < 8; ++nf) {
#pragma unroll
            for (int e = 0; e < 4; ++e) {
                float v = s[nf][e] * SCALE;
                if (diag) {
                    int col = j0 + nf * 8 + tg * 2 + (e & 1);
                    int row = qrow + ((e >> 1) << 3);
                    if (col > row) v = -1e30f;
                }
                s[nf][e] = v;
            }
        }

        float tm_g = -1e30f, tm_g8 = -1e30f;
#pragma unroll
        for (int nf = 0; nf < 8; ++nf) {
            tm_g  = fmaxf(tm_g,  fmaxf(s[nf][0], s[nf][1]));
            tm_g8 = fmaxf(tm_g8, fmaxf(s[nf][2], s[nf][3]));
        }
        tm_g  = fmaxf(tm_g,  __shfl_xor_sync(0xffffffffu, tm_g, 1));
        tm_g  = fmaxf(tm_g,  __shfl_xor_sync(0xffffffffu, tm_g, 2));
        tm_g8 = fmaxf(tm_g8, __shfl_xor_sync(0xffffffffu, tm_g8, 1));
        tm_g8 = fmaxf(tm_g8, __shfl_xor_sync(0xffffffffu, tm_g8, 2));

        float mn_g = fmaxf(m_g, tm_g);
        float mn_g8 = fmaxf(m_g8, tm_g8);
        float alpha_g = expf(m_g - mn_g);
        float alpha_g8 = expf(m_g8 - mn_g8);
        m_g = mn_g; m_g8 = mn_g8;

        float sum_g = 0.f, sum_g8 = 0.f;
#pragma unroll
        for (int nf = 0; nf < 8; ++nf) {
            s[nf][0] = expf(s[nf][0] - mn_g);
            s[nf][1] = expf(s[nf][1] - mn_g);
            s[nf][2] = expf(s[nf][2] - mn_g8);
            s[nf][3] = expf(s[nf][3] - mn_g8);
            sum_g += s[nf][0] + s[nf][1];
            sum_g8 += s[nf][2] + s[nf][3];
        }
        sum_g  += __shfl_xor_sync(0xffffffffu, sum_g, 1);
        sum_g  += __shfl_xor_sync(0xffffffffu, sum_g, 2);
        sum_g8 += __shfl_xor_sync(0xffffffffu, sum_g8, 1);
        sum_g8 += __shfl_xor_sync(0xffffffffu, sum_g8, 2);
        l_g = l_g * alpha_g + sum_g;
        l_g8 = l_g8 * alpha_g8 + sum_g8;

#pragma unroll
        for (int nf = 0; nf < 8; ++nf) {
            o[nf][0] *= alpha_g;
            o[nf][1] *= alpha_g;
            o[nf][2] *= alpha_g8;
            o[nf][3] *= alpha_g8;
        }

#pragma unroll
        for (int kc = 0; kc < 4; ++kc) {
            uint32_t ph[4], pl[4];
            {
                const float* s0 = s[2 * kc];
                const float* s1 = s[2 * kc + 1];
                float h0 = __bfloat162float(__float2bfloat16(s0[0]));
                float h1 = __bfloat162float(__float2bfloat16(s0[1]));
                float h2 = __bfloat162float(__float2bfloat16(s0[2]));
                float h3 = __bfloat162float(__float2bfloat16(s0[3]));
                float h4 = __bfloat162float(__float2bfloat16(s1[0]));
                float h5 = __bfloat162float(__float2bfloat16(s1[1]));
                float h6 = __bfloat162float(__float2bfloat16(s1[2]));
                float h7 = __bfloat162float(__float2bfloat16(s1[3]));
                ph[0] = pack_bf2(h0, h1);
                ph[1] = pack_bf2(h2, h3);
                ph[2] = pack_bf2(h4, h5);
                ph[3] = pack_bf2(h6, h7);
                pl[0] = pack_bf2(s0[0] - h0, s0[1] - h1);
                pl[1] = pack_bf2(s0[2] - h2, s0[3] - h3);
                pl[2] = pack_bf2(s1[0] - h4, s1[1] - h5);
                pl[3] = pack_bf2(s1[2] - h6, s1[3] - h7);
            }
            const int kb = kc * 32 + tg * 4;
            uint32_t vh[8][2], vl[8][2];
#pragma unroll
            for (int nf = 0; nf < 8; ++nf) {
                const char* p = sV + (nf * 8 + g) * FL_PITCH + kb;
                vh[nf][0] = *(const uint32_t*)p;
                vh[nf][1] = *(const uint32_t*)(p + 16);
                const char* p2 = sVl + (nf * 8 + g) * FL_PITCH + kb;
                vl[nf][0] = *(const uint32_t*)p2;
                vl[nf][1] = *(const uint32_t*)(p2 + 16);
            }
#pragma unroll
            for (int nf = 0; nf < 8; ++nf) {
                mma16816(o[nf], ph, vh[nf]);
                mma16816(o[nf], ph, vl[nf]);
                mma16816(o[nf], pl, vh[nf]);
            }
        }

        __syncthreads();
        if (t + 2 < nT) load_stage(st, t + 2);
        CP_COMMIT();
    }

    const float inv_g = 1.0f / l_g;
    const float inv_g8 = 1.0f / l_g8;
#pragma unroll
    for (int nf = 0; nf < 8; ++nf) {
        const int col = h * DKK + nf * 8 + tg * 2;
        {
            float v0 = o[nf][0] * inv_g, v1 = o[nf][1] * inv_g;
            size_t addr = ((size_t)b * SS + qrow) * DD + col;
            __nv_bfloat162 hh = __floats2bfloat162_rn(v0, v1);
            *(uint32_t*)(g_ahi + addr) = *(uint32_t*)&hh;
            __nv_bfloat162 ll = __floats2bfloat162_rn(v0 - __bfloat162float(hh.x),
                                                      v1 - __bfloat162float(hh.y));
            *(uint32_t*)(g_alo + addr) = *(uint32_t*)&ll;
        }
        {
            float v0 = o[nf][2] * inv_g8, v1 = o[nf][3] * inv_g8;
            size_t addr = ((size_t)b * SS + qrow + 8) * DD + col;
            __nv_bfloat162 hh = __floats2bfloat162_rn(v0, v1);
            *(uint32_t*)(g_ahi + addr) = *(uint32_t*)&hh;
            __nv_bfloat162 ll = __floats2bfloat162_rn(v0 - __bfloat162float(hh.x),
                                                      v1 - __bfloat162float(hh.y));
            *(uint32_t*)(g_alo + addr) = *(uint32_t*)&ll;
        }
    }
}

// ---------------------------------------------------------------------------
extern "C" void kernel_launch(void* const* d_in, const int* in_sizes, int n_in,
                              void* d_out, int out_size)
{
    const float* x  = (const float*)d_in[0];
    const int*   tp = (const int*)d_in[1];
    const float* Wq = (const float*)d_in[2];
    const float* bq = (const float*)d_in[3];
    const float* Wk = (const float*)d_in[4];
    const float* bk = (const float*)d_in[5];
    const float* Wv = (const float*)d_in[6];
    const float* bv = (const float*)d_in[7];
    const float* Wo = (const float*)d_in[8];
    const float* bo = (const float*)d_in[9];
    float* out = (float*)d_out;

    __nv_bfloat16 *xhi, *xlo, *ahi, *alo, *whi, *wlo;
    cudaGetSymbolAddress((void**)&xhi, g_xhi);
    cudaGetSymbolAddress((void**)&xlo, g_xlo);
    cudaGetSymbolAddress((void**)&ahi, g_ahi);
    cudaGetSymbolAddress((void**)&alo, g_alo);
    cudaGetSymbolAddress((void**)&whi, g_whi);
    cudaGetSymbolAddress((void**)&wlo, g_wlo);

    static int attr_set = 0;
    if (!attr_set) {
        cudaFuncSetAttribute(mma_gemm<true>,
                             cudaFuncAttributeMaxDynamicSharedMemorySize, GEMM_SMEM);
        cudaFuncSetAttribute(mma_gemm<false>,
                             cudaFuncAttributeMaxDynamicSharedMemorySize, GEMM_SMEM);
        cudaFuncSetAttribute(flash_mma,
                             cudaFuncAttributeMaxDynamicSharedMemorySize, FL_SMEM);
        attr_set = 1;
    }

    const int nX = MM * DD;
    dim3 bW(32, 8);

    convert_hl<<<nX / 4 / 256, 256>>>(x, xhi, xlo, nX);
    convert_w4_t<<<dim3(32, 32, 4), bW>>>(Wq, Wk, Wv, Wo);

    // Fused QKV projection with RoPE epilogue: N=3072, 768 CTAs
    dim3 gQKV(3 * DD / 128, MM / 128);  // (24, 32)
    mma_gemm<true><<<gQKV, 256, GEMM_SMEM>>>(xhi, xlo, whi, wlo,
                                             bq, bk, bv, tp, nullptr);

    // Flash attention: 64-row q-tiles, 1024 CTAs, target 3 CTAs/SM
    dim3 gFlash(SS / 64, HH, BB);  // (32, 16, 2)
    flash_mma<<<gFlash, 128, FL_SMEM>>>();

    // O projection (weight section 3)
    dim3 gO(DD / 128, MM / 128);  // (8, 32)
    mma_gemm<false><<<gO, 256, GEMM_SMEM>>>(ahi, alo,
                                            whi + (size_t)3 * DD * DD,
                                            wlo + (size_t)3 * DD * DD,
                                            bo, bo, bo, tp, out);
}